// round 9
// baseline (speedup 1.0000x reference)
#include <cuda_runtime.h>
#include <cstdint>

#define D_MODEL 1024
#define NB 4
#define NCTA 128
#define NTHREADS 256          // 8 warps, one row per warp
#define TP1_MAX 2049
#define BOS 0

typedef unsigned long long u64;

// Tagged hidden state: one 64-bit word per element = {tag:32 | value_bits:32}.
// Producer of h_t stores tag = t+1 in the SAME 8-byte scalar relaxed-atomic
// store as the value (single-copy atomic -> no tearing). Double-buffered by
// t&1; dependency ordering bounds CTA skew so tags never overtake a reader.
__device__ u64 g_hbuf2[2][NB][D_MODEL];

__global__ void rnn_init_kernel() {
    int i = blockIdx.x * blockDim.x + threadIdx.x;
    if (i < 2 * NB * D_MODEL)
        reinterpret_cast<u64*>(g_hbuf2)[i] = 0ull;   // tag 0 == h_{-1}
}

__device__ __forceinline__ u64 ld_relaxed_u64(const u64* p) {
    u64 v;
    asm volatile("ld.relaxed.gpu.global.u64 %0, [%1];" : "=l"(v) : "l"(p) : "memory");
    return v;
}
__device__ __forceinline__ void st_relaxed_u64(u64* p, u64 v) {
    asm volatile("st.relaxed.gpu.global.u64 [%0], %1;" :: "l"(p), "l"(v) : "memory");
}

// Persistent kernel: 128 CTAs x 8 rows (one row per warp, W row in registers).
// Iterations are BATCH-PAIRS (t, g): g=0 handles b{0,1}, g=1 handles b{2,3}.
// One __syncthreads per pair (half the barriers of R8), two independent
// matvec+reduce chains per warp per iteration (2x ILP).
__global__ void __launch_bounds__(NTHREADS, 1)
rnn_scan_kernel(const int*   __restrict__ ids,
                const float* __restrict__ emb,
                const float* __restrict__ W,
                float*       __restrict__ out,
                int Tp1)
{
    __shared__ int    ids_sm[NB * TP1_MAX];     // tokens incl. BOS
    __shared__ float4 hsm[2][2][D_MODEL / 4];   // [g][j] = staged h of batch 2g+j

    const int tid  = threadIdx.x;
    const int lane = tid & 31;
    const int row  = blockIdx.x * 8 + (tid >> 5);

    // ---- W row -> registers: 32 floats/lane ----
    const float4* __restrict__ Wv = reinterpret_cast<const float4*>(W);
    float4 wr[8];
#pragma unroll
    for (int k = 0; k < 8; ++k) wr[k] = Wv[(size_t)row * 256 + lane + 32 * k];

    // ---- stage token ids with BOS prepended ----
    const int T = Tp1 - 1;
    for (int i = tid; i < NB * Tp1; i += NTHREADS) {
        int b = i / Tp1;
        int t = i - b * Tp1;
        ids_sm[i] = (t == 0) ? BOS : ids[b * T + (t - 1)];
    }
    {   // inputs of iteration (0,0): h_{-1}(0), h_{-1}(1) = 0
        float4 z = make_float4(0.f, 0.f, 0.f, 0.f);
        hsm[0][0][tid] = z;
        hsm[0][1][tid] = z;
    }
    __syncthreads();

    // ---- embedding prefetch (lane0): statically-indexed per chain ----
    float e_pref[NB];
    if (lane == 0) {
#pragma unroll
        for (int b = 0; b < NB; ++b)
            e_pref[b] = emb[(size_t)ids_sm[b * Tp1] * D_MODEL + row];
    }

    for (int t = 0; t < Tp1; ++t) {
#pragma unroll
        for (int g = 0; g < 2; ++g) {
            const int b0 = 2 * g, b1 = 2 * g + 1;

            // ---- B. issue tagged stage loads for the NEXT iteration ----
            // next iter: (t, 1) if g==0 else (t+1, 0); inputs h_{tn-1}(2gn+j)
            const int gn = g ^ 1;
            const int tn = (g == 1) ? t + 1 : t;
            const bool have_next = (tn < Tp1);
            const u64* s0 = nullptr;
            const u64* s1 = nullptr;
            u64 p00, p01, p02, p03, p10, p11, p12, p13;
            const unsigned exp = (unsigned)tn;       // tag of h_{tn-1}
            if (have_next) {
                const int slot = (tn + 1) & 1;       // h_{tn-1} lives here
                s0 = &g_hbuf2[slot][2 * gn + 0][4 * tid];
                s1 = &g_hbuf2[slot][2 * gn + 1][4 * tid];
                p00 = ld_relaxed_u64(s0 + 0); p01 = ld_relaxed_u64(s0 + 1);
                p02 = ld_relaxed_u64(s0 + 2); p03 = ld_relaxed_u64(s0 + 3);
                p10 = ld_relaxed_u64(s1 + 0); p11 = ld_relaxed_u64(s1 + 1);
                p12 = ld_relaxed_u64(s1 + 2); p13 = ld_relaxed_u64(s1 + 3);
            }

            // ---- C. two interleaved matvecs (full row per warp each) ----
            const float4* __restrict__ hA = hsm[g][0];
            const float4* __restrict__ hB = hsm[g][1];
            float a0 = 0.f, a1 = 0.f, a2 = 0.f, a3 = 0.f;
            float c0 = 0.f, c1 = 0.f, c2 = 0.f, c3 = 0.f;
#pragma unroll
            for (int kk = 0; kk < 8; kk += 4) {
                float4 u0 = hA[lane + 32 * (kk + 0)];
                float4 u1 = hA[lane + 32 * (kk + 1)];
                float4 u2 = hA[lane + 32 * (kk + 2)];
                float4 u3 = hA[lane + 32 * (kk + 3)];
                float4 v0 = hB[lane + 32 * (kk + 0)];
                float4 v1 = hB[lane + 32 * (kk + 1)];
                float4 v2 = hB[lane + 32 * (kk + 2)];
                float4 v3 = hB[lane + 32 * (kk + 3)];
                a0 += wr[kk + 0].x * u0.x; c0 += wr[kk + 0].x * v0.x;
                a0 += wr[kk + 0].y * u0.y; c0 += wr[kk + 0].y * v0.y;
                a0 += wr[kk + 0].z * u0.z; c0 += wr[kk + 0].z * v0.z;
                a0 += wr[kk + 0].w * u0.w; c0 += wr[kk + 0].w * v0.w;
                a1 += wr[kk + 1].x * u1.x; c1 += wr[kk + 1].x * v1.x;
                a1 += wr[kk + 1].y * u1.y; c1 += wr[kk + 1].y * v1.y;
                a1 += wr[kk + 1].z * u1.z; c1 += wr[kk + 1].z * v1.z;
                a1 += wr[kk + 1].w * u1.w; c1 += wr[kk + 1].w * v1.w;
                a2 += wr[kk + 2].x * u2.x; c2 += wr[kk + 2].x * v2.x;
                a2 += wr[kk + 2].y * u2.y; c2 += wr[kk + 2].y * v2.y;
                a2 += wr[kk + 2].z * u2.z; c2 += wr[kk + 2].z * v2.z;
                a2 += wr[kk + 2].w * u2.w; c2 += wr[kk + 2].w * v2.w;
                a3 += wr[kk + 3].x * u3.x; c3 += wr[kk + 3].x * v3.x;
                a3 += wr[kk + 3].y * u3.y; c3 += wr[kk + 3].y * v3.y;
                a3 += wr[kk + 3].z * u3.z; c3 += wr[kk + 3].z * v3.z;
                a3 += wr[kk + 3].w * u3.w; c3 += wr[kk + 3].w * v3.w;
            }
            float a = (a0 + a1) + (a2 + a3);
            float c = (c0 + c1) + (c2 + c3);
            // interleaved butterfly reduces (independent chains)
#pragma unroll
            for (int off = 16; off > 0; off >>= 1) {
                a += __shfl_xor_sync(0xffffffffu, a, off);
                c += __shfl_xor_sync(0xffffffffu, c, off);
            }

            // ---- D. epilogue: publish both h_t values (tagged u64) ----
            if (lane == 0) {
                float va = a + e_pref[b0];
                float vc = c + e_pref[b1];
                const u64 tg = (u64)(unsigned)(t + 1) << 32;
                st_relaxed_u64(&g_hbuf2[t & 1][b0][row], tg | (u64)__float_as_uint(va));
                st_relaxed_u64(&g_hbuf2[t & 1][b1][row], tg | (u64)__float_as_uint(vc));
                out[((size_t)b0 * Tp1 + t) * D_MODEL + row] = va;
                out[((size_t)b1 * Tp1 + t) * D_MODEL + row] = vc;
                if (t + 1 < Tp1) {   // prefetch for (t+1, b), consumed 2 iters later
                    e_pref[b0] = emb[(size_t)ids_sm[b0 * Tp1 + t + 1] * D_MODEL + row];
                    e_pref[b1] = emb[(size_t)ids_sm[b1 * Tp1 + t + 1] * D_MODEL + row];
                }
            }

            // ---- E. tag check (the ONLY wait) + publish stage to smem ----
            if (have_next) {
                while ((unsigned)(p00 >> 32) != exp || (unsigned)(p01 >> 32) != exp ||
                       (unsigned)(p02 >> 32) != exp || (unsigned)(p03 >> 32) != exp) {
                    p00 = ld_relaxed_u64(s0 + 0); p01 = ld_relaxed_u64(s0 + 1);
                    p02 = ld_relaxed_u64(s0 + 2); p03 = ld_relaxed_u64(s0 + 3);
                }
                while ((unsigned)(p10 >> 32) != exp || (unsigned)(p11 >> 32) != exp ||
                       (unsigned)(p12 >> 32) != exp || (unsigned)(p13 >> 32) != exp) {
                    p10 = ld_relaxed_u64(s1 + 0); p11 = ld_relaxed_u64(s1 + 1);
                    p12 = ld_relaxed_u64(s1 + 2); p13 = ld_relaxed_u64(s1 + 3);
                }
                hsm[gn][0][tid] = make_float4(__uint_as_float((unsigned)p00),
                                              __uint_as_float((unsigned)p01),
                                              __uint_as_float((unsigned)p02),
                                              __uint_as_float((unsigned)p03));
                hsm[gn][1][tid] = make_float4(__uint_as_float((unsigned)p10),
                                              __uint_as_float((unsigned)p11),
                                              __uint_as_float((unsigned)p12),
                                              __uint_as_float((unsigned)p13));
            }

            // ---- G. single barrier per PAIR of units ----
            __syncthreads();
        }
    }
}

extern "C" void kernel_launch(void* const* d_in, const int* in_sizes, int n_in,
                              void* d_out, int out_size) {
    const int*   ids = (const int*)d_in[0];
    const float* emb = (const float*)d_in[1];
    const float* W   = (const float*)d_in[2];
    float* out = (float*)d_out;

    int Tp1 = out_size / (NB * D_MODEL);   // 2049 for the reference shapes
    if (Tp1 > TP1_MAX) Tp1 = TP1_MAX;

    rnn_init_kernel<<<32, 256>>>();
    rnn_scan_kernel<<<NCTA, NTHREADS>>>(ids, emb, W, out, Tp1);
}